// round 7
// baseline (speedup 1.0000x reference)
#include <cuda_runtime.h>

// LineSpectralPairsStabilityCheck: (256, 4096, 33) fp32, 1,048,576 rows.
// Per row: keep [0]; 4 passes of {31-step neighbor-separation scan + clip}.
// Issue-bound with a serial per-row chain -> 2 rows per thread, ALL SCALAR
// (two independent dependency chains per warp; no packed-reg mov overhead).
// Smem-staged coalesced float4 streaming global I/O.

#define W 33
#define THREADS 128
#define ROWS_PER_BLOCK 256
#define TILE_ELEMS (ROWS_PER_BLOCK * W)   // 8448 floats = 33792 B smem
#define TILE_VEC4 (TILE_ELEMS / 4)        // 2112

__global__ void __launch_bounds__(THREADS)
lsp_stability_kernel(const float* __restrict__ in, float* __restrict__ out)
{
    __shared__ float sm[TILE_ELEMS];

    const int t = threadIdx.x;
    const long long base = (long long)blockIdx.x * TILE_ELEMS;

    // ---- coalesced vectorized streaming load of the block tile ----
    const float4* __restrict__ in4 = (const float4*)(in + base);
    float4* sm4 = (float4*)sm;
    #pragma unroll
    for (int i = t; i < TILE_VEC4; i += THREADS)
        sm4[i] = __ldcs(&in4[i]);
    __syncthreads();

    // ---- thread t owns rows t and t+128 (both stride-33 -> conflict-free;
    //      row offset 33*128 == 0 mod 32). Channel 0 (K) passes through smem.
    float a[W], b[W];   // [0] unused
    const int ra = t * W;
    const int rb = (t + THREADS) * W;
    #pragma unroll
    for (int i = 1; i < W; i++) {
        a[i] = sm[ra + i];
        b[i] = sm[rb + i];
    }

    const float pi_f  = 3.14159265358979323846f;
    const float min_d = 0.01f * pi_f / 33.0f;   // RATE * pi / (LSP_ORDER + 1)
    const float hi    = pi_f - min_d;

    #pragma unroll
    for (int it = 0; it < 4; it++) {
        // Two independent scalar chains, interleaved.
        // chain per step: u = c + m (FADD) -> s = max(u,0) (FMNMX)
        //              -> c = fma(s, 0.5, nxt) (FFMA); rest off-chain.
        float ca = a[1];
        float cb = b[1];
        #pragma unroll
        for (int i = 2; i <= 32; i++) {
            float na = a[i];
            float nb = b[i];
            float ma = min_d - na;
            float mb = min_d - nb;
            float ua = ca + ma;
            float ub = cb + mb;
            float sa = fmaxf(ua, 0.0f);
            float sb = fmaxf(ub, 0.0f);
            float oa = fmaf(sa, -0.5f, ca);
            float ob = fmaf(sb, -0.5f, cb);
            oa = fmaxf(oa, min_d);
            ob = fmaxf(ob, min_d);
            a[i - 1] = fminf(oa, hi);
            b[i - 1] = fminf(ob, hi);
            ca = fmaf(sa, 0.5f, na);
            cb = fmaf(sb, 0.5f, nb);
        }
        a[32] = fminf(fmaxf(ca, min_d), hi);
        b[32] = fminf(fmaxf(cb, min_d), hi);
    }

    // ---- write rows back to private smem cells (channel 0 untouched) ----
    #pragma unroll
    for (int i = 1; i < W; i++) {
        sm[ra + i] = a[i];
        sm[rb + i] = b[i];
    }
    __syncthreads();

    // ---- coalesced vectorized streaming store ----
    float4* __restrict__ out4 = (float4*)(out + base);
    #pragma unroll
    for (int i = t; i < TILE_VEC4; i += THREADS)
        __stcs(&out4[i], sm4[i]);
}

extern "C" void kernel_launch(void* const* d_in, const int* in_sizes, int n_in,
                              void* d_out, int out_size)
{
    const float* in = (const float*)d_in[0];
    float* out = (float*)d_out;

    const int total = in_sizes[0];                 // 256*4096*33 = 34,603,008
    const int rows = total / W;                    // 1,048,576
    const int blocks = rows / ROWS_PER_BLOCK;      // 4096 (exact)

    lsp_stability_kernel<<<blocks, THREADS>>>(in, out);
}

// round 8
// speedup vs baseline: 1.3609x; 1.3609x over previous
#include <cuda_runtime.h>

// LineSpectralPairsStabilityCheck: (256, 4096, 33) fp32, 1,048,576 rows.
// Per row: keep [0]; 4 passes of {31-step neighbor-separation scan + clip}.
// DRAM-bound plateau -> decouple warps: each warp stages its own 32 rows
// through a private smem slice with __syncwarp only (no block barrier), so
// load/compute/store phases of different warps interleave and keep HBM busy.

#define W 33
#define THREADS 128
#define WARPS (THREADS / 32)
#define ROWS_PER_WARP 32
#define WSLICE (ROWS_PER_WARP * W)        // 1056 floats = 4224 B per warp
#define WSLICE_V4 (WSLICE / 4)            // 264 float4
#define TILE_ELEMS (WARPS * WSLICE)       // 4224 floats = 16896 B

__global__ void __launch_bounds__(THREADS)
lsp_stability_kernel(const float* __restrict__ in, float* __restrict__ out)
{
    __shared__ float sm[TILE_ELEMS];

    const int t    = threadIdx.x;
    const int warp = t >> 5;
    const int lane = t & 31;

    const int wbase = warp * WSLICE;                    // this warp's smem slice
    const long long gbase = (long long)blockIdx.x * TILE_ELEMS + wbase;

    // ---- warp-local coalesced streaming load (4224 B contiguous) ----
    const float4* __restrict__ in4 = (const float4*)(in + gbase);
    float4* sw4 = (float4*)(sm + wbase);
    #pragma unroll
    for (int i = lane; i < WSLICE_V4; i += 32)
        sw4[i] = __ldcs(&in4[i]);
    __syncwarp();

    // ---- lane owns one row of the slice (stride-33: conflict-free) ----
    // Channel 0 (K) passes through smem untouched.
    const int rbase = wbase + lane * W;
    float v[W];   // v[0] unused
    #pragma unroll
    for (int i = 1; i < W; i++)
        v[i] = sm[rbase + i];

    const float pi_f  = 3.14159265358979323846f;
    const float min_d = 0.01f * pi_f / 33.0f;   // RATE * pi / (LSP_ORDER + 1)
    const float hi    = pi_f - min_d;

    #pragma unroll
    for (int it = 0; it < 4; it++) {
        // chain per step: u = c + m (FADD) -> s = max(u,0) (FMNMX)
        //              -> c = fma(s, 0.5, nxt) (FFMA); rest off-chain.
        float c = v[1];
        #pragma unroll
        for (int i = 2; i <= 32; i++) {
            float nxt = v[i];
            float m = min_d - nxt;            // off-chain
            float u = c + m;                  // chain
            float s = fmaxf(u, 0.0f);         // chain
            float o = fmaf(s, -0.5f, c);      // off-chain output
            o = fmaxf(o, min_d);
            v[i - 1] = fminf(o, hi);
            c = fmaf(s, 0.5f, nxt);           // chain (carried unclipped)
        }
        v[32] = fminf(fmaxf(c, min_d), hi);
    }

    // ---- write row back to private smem cell ----
    #pragma unroll
    for (int i = 1; i < W; i++)
        sm[rbase + i] = v[i];
    __syncwarp();

    // ---- warp-local coalesced streaming store ----
    float4* __restrict__ out4 = (float4*)(out + gbase);
    #pragma unroll
    for (int i = lane; i < WSLICE_V4; i += 32)
        __stcs(&out4[i], sw4[i]);
}

extern "C" void kernel_launch(void* const* d_in, const int* in_sizes, int n_in,
                              void* d_out, int out_size)
{
    const float* in = (const float*)d_in[0];
    float* out = (float*)d_out;

    const int total = in_sizes[0];            // 256*4096*33 = 34,603,008
    const int rows = total / W;               // 1,048,576
    const int blocks = rows / (WARPS * ROWS_PER_WARP);  // 8192 (exact)

    lsp_stability_kernel<<<blocks, THREADS>>>(in, out);
}